// round 15
// baseline (speedup 1.0000x reference)
#include <cuda_runtime.h>
#include <cuda_bf16.h>
#include <cuda_fp16.h>
#include <cstdint>

#define N_NODES 50000
#define N_EDGES 800000
#define D_MAX   128
#define PAD_LG  6                            // 64 slots per row
#define PAD     (1 << PAD_LG)

// ---------------- scratch (allocation-free: __device__ globals) ----------------
__device__ int      g_cnt[N_NODES];         // zero-initialized; invariant: zero at graph entry
__device__ int      g_deg[N_NODES];
__device__ uint32_t g_csr[(size_t)N_NODES * PAD]; // packed edge: src:u16 | fp16(w)<<16
__device__ float    g_sink[2048];           // warm-kernel sink
__device__ __half   g_bufA[(size_t)N_NODES * D_MAX];
__device__ __half   g_bufB[(size_t)N_NODES * D_MAX];
__device__ __nv_bfloat16 g_whi1[128 * 128], g_wlo1[128 * 128];
__device__ __nv_bfloat16 g_whi2[128 * 128], g_wlo2[128 * 128];
__device__ __nv_bfloat16 g_whi3[128 * 64],  g_wlo3[128 * 64];

// ================= helpers =================
__device__ __forceinline__ uint32_t smem_u32(const void* p) {
    uint32_t a;
    asm("{ .reg .u64 t; cvta.to.shared.u64 t, %1; cvt.u32.u64 %0, t; }" : "=r"(a) : "l"(p));
    return a;
}

// pack float2 -> bf16x2 (hi part) and residual bf16x2 (lo part)
__device__ __forceinline__ void bf16_split(float2 f, uint32_t& h, uint32_t& l) {
    asm("cvt.rn.bf16x2.f32 %0, %1, %2;" : "=r"(h) : "f"(f.y), "f"(f.x));  // hi<-f.y, lo<-f.x
    float h0 = __uint_as_float((h & 0x0000FFFFu) << 16);
    float h1 = __uint_as_float(h & 0xFFFF0000u);
    float l0 = f.x - h0;
    float l1 = f.y - h1;
    asm("cvt.rn.bf16x2.f32 %0, %1, %2;" : "=r"(l) : "f"(l1), "f"(l0));
}

// 2-element load as float2 from either fp32 or fp16 source
__device__ __forceinline__ float2 ldx2(const float* p) { return *(const float2*)p; }
__device__ __forceinline__ float2 ldx2(const __half* p) {
    return __half22float2(*(const __half2*)p);
}

__device__ __forceinline__ uint32_t pack_edge(int src, float w) {
    return (uint32_t)(src & 0xFFFF) |
           ((uint32_t)__half_as_ushort(__float2half_rn(w)) << 16);
}

#define LDSM4(d0, d1, d2, d3, addr)                                                \
    asm volatile("ldmatrix.sync.aligned.m8n8.x4.shared.b16 {%0,%1,%2,%3}, [%4];"   \
                 : "=r"(d0), "=r"(d1), "=r"(d2), "=r"(d3) : "r"(addr))

#define MMA16816(c, a, b0_, b1_)                                                   \
    asm volatile("mma.sync.aligned.m16n8k16.row.col.f32.bf16.bf16.f32 "            \
                 "{%0,%1,%2,%3}, {%4,%5,%6,%7}, {%8,%9}, {%0,%1,%2,%3};"           \
                 : "+f"((c)[0]), "+f"((c)[1]), "+f"((c)[2]), "+f"((c)[3])          \
                 : "r"((a)[0]), "r"((a)[1]), "r"((a)[2]), "r"((a)[3]),             \
                   "r"(b0_), "r"(b1_))

// ---------------- CSR build (single pass, padded layout, packed 32-bit edges) ----------
__global__ void k_scatter(const int* __restrict__ ei, const float* __restrict__ ew) {
    int i4 = blockIdx.x * blockDim.x + threadIdx.x;
    if (i4 * 4 < N_EDGES) {
        int4   d = ((const int4*)ei)[i4];
        int4   s = ((const int4*)(ei + N_EDGES))[i4];
        float4 w = ((const float4*)ew)[i4];
        int r;
        r = atomicAdd(&g_cnt[d.x], 1); g_csr[((size_t)d.x << PAD_LG) + r] = pack_edge(s.x, w.x);
        r = atomicAdd(&g_cnt[d.y], 1); g_csr[((size_t)d.y << PAD_LG) + r] = pack_edge(s.y, w.y);
        r = atomicAdd(&g_cnt[d.z], 1); g_csr[((size_t)d.z << PAD_LG) + r] = pack_edge(s.z, w.z);
        r = atomicAdd(&g_cnt[d.w], 1); g_csr[((size_t)d.w << PAD_LG) + r] = pack_edge(s.w, w.w);
    }
}

// snapshot degrees + restore the zero-invariant for the next replay
__global__ void k_degcopy() {
    int i = blockIdx.x * blockDim.x + threadIdx.x;
    if (i < N_NODES) {
        g_deg[i] = g_cnt[i];
        g_cnt[i] = 0;
    }
}

// ---------------- L2 warmer: pull X (25.6 MB) into L2 before gemm1 ----------------
__global__ void k_warm(const float* __restrict__ X) {
    const int stride = gridDim.x * blockDim.x;
    float acc = 0.f;
    for (int i = blockIdx.x * blockDim.x + threadIdx.x;
         i < N_NODES * D_MAX / 4; i += stride) {
        float4 v = ((const float4*)X)[i];
        acc += v.x + v.y + v.z + v.w;
    }
    if (threadIdx.x == 0) g_sink[blockIdx.x & 2047] = acc;
}

// ---------------- W prep: W[K=128, DOUT] fp32 -> W^T hi/lo bf16 [DOUT, 128] ----------------
__global__ void k_wprep(const float* __restrict__ W, int dout,
                        __nv_bfloat16* __restrict__ whi, __nv_bfloat16* __restrict__ wlo) {
    int idx = blockIdx.x * blockDim.x + threadIdx.x;
    if (idx < 128 * dout) {
        int k = idx / dout, n = idx % dout;
        float f = W[idx];
        __nv_bfloat16 h = __float2bfloat16_rn(f);
        __nv_bfloat16 l = __float2bfloat16_rn(f - __bfloat162float(h));
        whi[n * 128 + k] = h;
        wlo[n * 128 + k] = l;
    }
}

// ---------------- tensor-core GEMM via mma.sync: Out(fp16) = X @ W, bf16x3 split --------
// XT = float (layer 1) or __half (layers 2/3). 128-row CTA, 8 warps x 16 rows.
template <int DOUT, typename XT>
__global__ void __launch_bounds__(256) k_gemm_mma(const XT* __restrict__ X,
                                                  const __nv_bfloat16* __restrict__ whi,
                                                  const __nv_bfloat16* __restrict__ wlo,
                                                  __half* __restrict__ Out) {
    constexpr int NT2    = DOUT / 16;     // 8 or 4
    constexpr int STRIDE = 136;           // bf16 elems per smem row (pad 8)

    extern __shared__ __nv_bfloat16 bs[];
    __nv_bfloat16* Bh = bs;
    __nv_bfloat16* Bl = bs + DOUT * STRIDE;

    const int tid  = threadIdx.x;
    const int lane = tid & 31;
    const int wid  = tid >> 5;

    for (int t = tid; t < DOUT * 16; t += 256) {
        int n = t >> 4, c = t & 15;
        ((uint4*)(Bh + n * STRIDE))[c] = ((const uint4*)(whi + n * 128))[c];
        ((uint4*)(Bl + n * STRIDE))[c] = ((const uint4*)(wlo + n * 128))[c];
    }
    __syncthreads();

    const uint32_t bh_base = smem_u32(Bh);
    const uint32_t bl_base = smem_u32(Bl);

    const int r0 = blockIdx.x * 128 + wid * 16 + (lane >> 2);
    const int r1 = r0 + 8;
    const bool v0 = r0 < N_NODES, v1 = r1 < N_NODES;
    const int kc = (lane & 3) * 2;
    const XT* p0 = X + (size_t)r0 * 128 + kc;
    const XT* p1 = X + (size_t)r1 * 128 + kc;

    const uint32_t lm_row  = (lane & 7) + ((lane >> 4) << 3);
    const uint32_t lm_koff = ((lane >> 3) & 1) * 8;

    float acc[2 * NT2][4];
    #pragma unroll
    for (int i = 0; i < 2 * NT2; i++)
        #pragma unroll
        for (int j = 0; j < 4; j++) acc[i][j] = 0.0f;

    #pragma unroll
    for (int ks = 0; ks < 8; ks++) {
        const int k0 = ks * 16;
        float2 z = make_float2(0.f, 0.f);
        float2 x00 = v0 ? ldx2(p0 + k0)     : z;
        float2 x01 = v0 ? ldx2(p0 + k0 + 8) : z;
        float2 x10 = v1 ? ldx2(p1 + k0)     : z;
        float2 x11 = v1 ? ldx2(p1 + k0 + 8) : z;
        uint32_t ah[4], al[4];
        bf16_split(x00, ah[0], al[0]);
        bf16_split(x10, ah[1], al[1]);
        bf16_split(x01, ah[2], al[2]);
        bf16_split(x11, ah[3], al[3]);

        #pragma unroll
        for (int nt = 0; nt < NT2; nt++) {
            uint32_t off = ((nt * 16 + lm_row) * STRIDE + (uint32_t)k0 + lm_koff) * 2;
            uint32_t h0, h1, h2, h3, l0, l1, l2, l3;
            LDSM4(h0, h1, h2, h3, bh_base + off);
            LDSM4(l0, l1, l2, l3, bl_base + off);
            MMA16816(acc[2 * nt],     ah, h0, h1);
            MMA16816(acc[2 * nt],     ah, l0, l1);
            MMA16816(acc[2 * nt],     al, h0, h1);
            MMA16816(acc[2 * nt + 1], ah, h2, h3);
            MMA16816(acc[2 * nt + 1], ah, l2, l3);
            MMA16816(acc[2 * nt + 1], al, h2, h3);
        }
    }

    #pragma unroll
    for (int nt = 0; nt < NT2; nt++) {
        int n0 = nt * 16 + kc;
        if (v0) {
            *(__half2*)(Out + (size_t)r0 * DOUT + n0)     = __floats2half2_rn(acc[2 * nt][0],     acc[2 * nt][1]);
            *(__half2*)(Out + (size_t)r0 * DOUT + n0 + 8) = __floats2half2_rn(acc[2 * nt + 1][0], acc[2 * nt + 1][1]);
        }
        if (v1) {
            *(__half2*)(Out + (size_t)r1 * DOUT + n0)     = __floats2half2_rn(acc[2 * nt][2],     acc[2 * nt][3]);
            *(__half2*)(Out + (size_t)r1 * DOUT + n0 + 8) = __floats2half2_rn(acc[2 * nt + 1][2], acc[2 * nt + 1][3]);
        }
    }
}

// ---------------- SpMM 128-wide: TWO warps per node (column halves of 64) --------------
// Each warp gathers 128B/row; doubles independent request streams for latency hiding.
template <bool RELU, typename OT>
__global__ void __launch_bounds__(256) k_spmm128(const __half* __restrict__ T,
                                                 const float* __restrict__ bias,
                                                 OT* __restrict__ H) {
    const int gw   = blockIdx.x * 8 + (threadIdx.x >> 5);
    const int node = gw >> 1;
    const int ch   = gw & 1;                 // column half: 0 -> cols 0..63, 1 -> 64..127
    const int lane = threadIdx.x & 31;
    if (node >= N_NODES) return;
    const int deg = g_deg[node];
    const uint32_t* row = g_csr + ((size_t)node << PAD_LG);
    const __half* Tc = T + ch * 64 + lane * 2;

    float2 acc = make_float2(0.f, 0.f);
    for (int eb = 0; eb < deg; eb += 32) {
        int e = eb + lane;
        uint32_t ed = 0;
        if (e < deg) ed = row[e];
        int m = min(32, deg - eb);
        #pragma unroll 8
        for (int j = 0; j < m; j++) {
            uint32_t pe = __shfl_sync(0xffffffffu, ed, j);
            int   sj = (int)(pe & 0xFFFFu);
            float wj = __half2float(__ushort_as_half((unsigned short)(pe >> 16)));
            float2 f = __half22float2(*(const __half2*)(Tc + (size_t)sj * 128));
            acc.x += wj * f.x; acc.y += wj * f.y;
        }
    }
    float2 b = ((const float2*)bias)[ch * 32 + lane];
    acc.x += b.x; acc.y += b.y;
    if (RELU) { acc.x = fmaxf(acc.x, 0.f); acc.y = fmaxf(acc.y, 0.f); }
    OT* o = H + (size_t)node * 128 + ch * 64 + lane * 2;
    if (sizeof(OT) == 2) {
        *(__half2*)o = __floats2half2_rn(acc.x, acc.y);
    } else {
        *(float2*)o = acc;
    }
}

// ---------------- SpMM 64-wide (one warp per node, unchanged) --------------------------
template <bool RELU, typename OT>
__global__ void __launch_bounds__(256) k_spmm64(const __half* __restrict__ T,
                                                const float* __restrict__ bias,
                                                OT* __restrict__ H) {
    const int warp = blockIdx.x * 8 + (threadIdx.x >> 5);
    const int lane = threadIdx.x & 31;
    if (warp >= N_NODES) return;
    const int deg = g_deg[warp];
    const uint32_t* row = g_csr + ((size_t)warp << PAD_LG);

    float2 acc = make_float2(0.f, 0.f);
    for (int eb = 0; eb < deg; eb += 32) {
        int e = eb + lane;
        uint32_t ed = 0;
        if (e < deg) ed = row[e];
        int m = min(32, deg - eb);
        #pragma unroll 8
        for (int j = 0; j < m; j++) {
            uint32_t pe = __shfl_sync(0xffffffffu, ed, j);
            int   sj = (int)(pe & 0xFFFFu);
            float wj = __half2float(__ushort_as_half((unsigned short)(pe >> 16)));
            float2 f = __half22float2(*(const __half2*)(T + (size_t)sj * 64 + lane * 2));
            acc.x += wj * f.x; acc.y += wj * f.y;
        }
    }
    float2 b = ((const float2*)bias)[lane];
    acc.x += b.x; acc.y += b.y;
    if (RELU) { acc.x = fmaxf(acc.x, 0.f); acc.y = fmaxf(acc.y, 0.f); }
    OT* o = H + (size_t)warp * 64 + lane * 2;
    if (sizeof(OT) == 2) {
        *(__half2*)o = __floats2half2_rn(acc.x, acc.y);
    } else {
        *(float2*)o = acc;
    }
}

// ---------------- launch ----------------
extern "C" void kernel_launch(void* const* d_in, const int* in_sizes, int n_in,
                              void* d_out, int out_size) {
    const float* x  = (const float*)d_in[0];
    const int*   ei = (const int*)  d_in[1];   // [2, E]: row0 = dst, row1 = src
    const float* ew = (const float*)d_in[2];
    const float* W1 = (const float*)d_in[3];
    const float* b1 = (const float*)d_in[4];
    const float* W2 = (const float*)d_in[5];
    const float* b2 = (const float*)d_in[6];
    const float* W3 = (const float*)d_in[7];
    const float* b3 = (const float*)d_in[8];
    float* out = (float*)d_out;

    void *pA, *pB, *ph1, *pl1, *ph2, *pl2, *ph3, *pl3;
    cudaGetSymbolAddress(&pA, g_bufA);
    cudaGetSymbolAddress(&pB, g_bufB);
    cudaGetSymbolAddress(&ph1, g_whi1); cudaGetSymbolAddress(&pl1, g_wlo1);
    cudaGetSymbolAddress(&ph2, g_whi2); cudaGetSymbolAddress(&pl2, g_wlo2);
    cudaGetSymbolAddress(&ph3, g_whi3); cudaGetSymbolAddress(&pl3, g_wlo3);
    __half* bufA = (__half*)pA;
    __half* bufB = (__half*)pB;
    __nv_bfloat16 *whi1 = (__nv_bfloat16*)ph1, *wlo1 = (__nv_bfloat16*)pl1;
    __nv_bfloat16 *whi2 = (__nv_bfloat16*)ph2, *wlo2 = (__nv_bfloat16*)pl2;
    __nv_bfloat16 *whi3 = (__nv_bfloat16*)ph3, *wlo3 = (__nv_bfloat16*)pl3;

    const int smem128 = 2 * 128 * 136 * 2;   // 69,632 B
    const int smem64  = 2 * 64  * 136 * 2;   // 34,816 B
    cudaFuncSetAttribute(k_gemm_mma<128, float>,  cudaFuncAttributeMaxDynamicSharedMemorySize, smem128);
    cudaFuncSetAttribute(k_gemm_mma<128, __half>, cudaFuncAttributeMaxDynamicSharedMemorySize, smem128);
    cudaFuncSetAttribute(k_gemm_mma<64,  __half>, cudaFuncAttributeMaxDynamicSharedMemorySize, smem64);

    // side stream + events (leaked deliberately: destroying during an active
    // capture is illegal, and kernel_launch runs only a handful of times)
    cudaStream_t s2;
    cudaStreamCreateWithFlags(&s2, cudaStreamNonBlocking);
    cudaEvent_t evFork, evJoin, evW23;
    cudaEventCreateWithFlags(&evFork, cudaEventDisableTiming);
    cudaEventCreateWithFlags(&evJoin, cudaEventDisableTiming);
    cudaEventCreateWithFlags(&evW23, cudaEventDisableTiming);

    const int e4_blocks   = (N_EDGES / 4 + 255) / 256;
    const int tiles       = (N_NODES + 127) / 128;      // 391
    const int sp128_blocks = (2 * N_NODES + 7) / 8;     // 12500 (2 warps/node)
    const int sp64_blocks  = (N_NODES + 7) / 8;         // 6250

    // ---- fork: branch B on s2 = warm X + wprep1 + GEMM1 ----
    cudaEventRecord(evFork, 0);
    cudaStreamWaitEvent(s2, evFork, 0);
    k_warm<<<1024, 256, 0, s2>>>(x);
    k_wprep<<<(128 * 128 + 255) / 256, 256, 0, s2>>>(W1, 128, whi1, wlo1);
    k_gemm_mma<128, float><<<tiles, 256, smem128, s2>>>(x, whi1, wlo1, bufA);
    cudaEventRecord(evJoin, s2);
    // wprep2/3 run on s2 during spmm1 (whi2/3 not read until gemm2/gemm3)
    k_wprep<<<(128 * 128 + 255) / 256, 256, 0, s2>>>(W2, 128, whi2, wlo2);
    k_wprep<<<(128 * 64 + 255) / 256, 256, 0, s2>>>(W3, 64, whi3, wlo3);
    cudaEventRecord(evW23, s2);

    // ---- branch A on origin stream = single-pass padded-CSR build ----
    k_scatter<<<e4_blocks, 256>>>(ei, ew);
    k_degcopy<<<(N_NODES + 255) / 256, 256>>>();

    // ---- join, then the serial layer chain ----
    cudaStreamWaitEvent(0, evJoin, 0);
    k_spmm128<true, __half><<<sp128_blocks, 256>>>(bufA, b1, bufB);
    cudaStreamWaitEvent(0, evW23, 0);
    k_gemm_mma<128, __half><<<tiles, 256, smem128>>>(bufB, whi2, wlo2, bufA);
    k_spmm128<true, __half><<<sp128_blocks, 256>>>(bufA, b2, bufB);
    k_gemm_mma<64, __half><<<tiles, 256, smem64>>>(bufB, whi3, wlo3, bufA);
    k_spmm64<false, float><<<sp64_blocks, 256>>>(bufA, b3, out);
}

// round 16
// speedup vs baseline: 1.1631x; 1.1631x over previous
#include <cuda_runtime.h>
#include <cuda_bf16.h>
#include <cuda_fp16.h>
#include <cstdint>

#define N_NODES 50000
#define N_EDGES 800000
#define D_MAX   128
#define PAD_LG  6                            // 64 slots per row
#define PAD     (1 << PAD_LG)

// ---------------- scratch (allocation-free: __device__ globals) ----------------
__device__ int      g_cnt[N_NODES];         // zero-initialized; invariant: zero at graph entry
__device__ int      g_deg[N_NODES];
__device__ uint32_t g_csr[(size_t)N_NODES * PAD]; // packed edge: src:u16 | fp16(w)<<16
__device__ float    g_sink[2048];           // warm-kernel sink
__device__ __half   g_bufA[(size_t)N_NODES * D_MAX];
__device__ __half   g_bufB[(size_t)N_NODES * D_MAX];
__device__ __nv_bfloat16 g_whi1[128 * 128], g_wlo1[128 * 128];
__device__ __nv_bfloat16 g_whi2[128 * 128], g_wlo2[128 * 128];
__device__ __nv_bfloat16 g_whi3[128 * 64],  g_wlo3[128 * 64];

// ================= helpers =================
__device__ __forceinline__ uint32_t smem_u32(const void* p) {
    uint32_t a;
    asm("{ .reg .u64 t; cvta.to.shared.u64 t, %1; cvt.u32.u64 %0, t; }" : "=r"(a) : "l"(p));
    return a;
}

// pack float2 -> bf16x2 (hi part) and residual bf16x2 (lo part)
__device__ __forceinline__ void bf16_split(float2 f, uint32_t& h, uint32_t& l) {
    asm("cvt.rn.bf16x2.f32 %0, %1, %2;" : "=r"(h) : "f"(f.y), "f"(f.x));  // hi<-f.y, lo<-f.x
    float h0 = __uint_as_float((h & 0x0000FFFFu) << 16);
    float h1 = __uint_as_float(h & 0xFFFF0000u);
    float l0 = f.x - h0;
    float l1 = f.y - h1;
    asm("cvt.rn.bf16x2.f32 %0, %1, %2;" : "=r"(l) : "f"(l1), "f"(l0));
}

// 2-element load as float2 from either fp32 or fp16 source
__device__ __forceinline__ float2 ldx2(const float* p) { return *(const float2*)p; }
__device__ __forceinline__ float2 ldx2(const __half* p) {
    return __half22float2(*(const __half2*)p);
}

__device__ __forceinline__ uint32_t pack_edge(int src, float w) {
    return (uint32_t)(src & 0xFFFF) |
           ((uint32_t)__half_as_ushort(__float2half_rn(w)) << 16);
}

#define LDSM4(d0, d1, d2, d3, addr)                                                \
    asm volatile("ldmatrix.sync.aligned.m8n8.x4.shared.b16 {%0,%1,%2,%3}, [%4];"   \
                 : "=r"(d0), "=r"(d1), "=r"(d2), "=r"(d3) : "r"(addr))

#define MMA16816(c, a, b0_, b1_)                                                   \
    asm volatile("mma.sync.aligned.m16n8k16.row.col.f32.bf16.bf16.f32 "            \
                 "{%0,%1,%2,%3}, {%4,%5,%6,%7}, {%8,%9}, {%0,%1,%2,%3};"           \
                 : "+f"((c)[0]), "+f"((c)[1]), "+f"((c)[2]), "+f"((c)[3])          \
                 : "r"((a)[0]), "r"((a)[1]), "r"((a)[2]), "r"((a)[3]),             \
                   "r"(b0_), "r"(b1_))

// ---------------- CSR build (single pass, padded layout, packed 32-bit edges) ----------
__global__ void k_scatter(const int* __restrict__ ei, const float* __restrict__ ew) {
    int i4 = blockIdx.x * blockDim.x + threadIdx.x;
    if (i4 * 4 < N_EDGES) {
        int4   d = ((const int4*)ei)[i4];
        int4   s = ((const int4*)(ei + N_EDGES))[i4];
        float4 w = ((const float4*)ew)[i4];
        int r;
        r = atomicAdd(&g_cnt[d.x], 1); g_csr[((size_t)d.x << PAD_LG) + r] = pack_edge(s.x, w.x);
        r = atomicAdd(&g_cnt[d.y], 1); g_csr[((size_t)d.y << PAD_LG) + r] = pack_edge(s.y, w.y);
        r = atomicAdd(&g_cnt[d.z], 1); g_csr[((size_t)d.z << PAD_LG) + r] = pack_edge(s.z, w.z);
        r = atomicAdd(&g_cnt[d.w], 1); g_csr[((size_t)d.w << PAD_LG) + r] = pack_edge(s.w, w.w);
    }
}

// snapshot degrees + restore the zero-invariant for the next replay
__global__ void k_degcopy() {
    int i = blockIdx.x * blockDim.x + threadIdx.x;
    if (i < N_NODES) {
        g_deg[i] = g_cnt[i];
        g_cnt[i] = 0;
    }
}

// ---------------- L2 warmer: pull X (25.6 MB) into L2 before gemm1 ----------------
__global__ void k_warm(const float* __restrict__ X) {
    const int stride = gridDim.x * blockDim.x;
    float acc = 0.f;
    for (int i = blockIdx.x * blockDim.x + threadIdx.x;
         i < N_NODES * D_MAX / 4; i += stride) {
        float4 v = ((const float4*)X)[i];
        acc += v.x + v.y + v.z + v.w;
    }
    if (threadIdx.x == 0) g_sink[blockIdx.x & 2047] = acc;
}

// ---------------- W prep: W[K=128, DOUT] fp32 -> W^T hi/lo bf16 [DOUT, 128] ----------------
__global__ void k_wprep(const float* __restrict__ W, int dout,
                        __nv_bfloat16* __restrict__ whi, __nv_bfloat16* __restrict__ wlo) {
    int idx = blockIdx.x * blockDim.x + threadIdx.x;
    if (idx < 128 * dout) {
        int k = idx / dout, n = idx % dout;
        float f = W[idx];
        __nv_bfloat16 h = __float2bfloat16_rn(f);
        __nv_bfloat16 l = __float2bfloat16_rn(f - __bfloat162float(h));
        whi[n * 128 + k] = h;
        wlo[n * 128 + k] = l;
    }
}

// ---------------- tensor-core GEMM via mma.sync: Out(fp16) = X @ W, bf16x3 split --------
// XT = float (layer 1) or __half (layers 2/3). 128-row CTA, 8 warps x 16 rows.
template <int DOUT, typename XT>
__global__ void __launch_bounds__(256) k_gemm_mma(const XT* __restrict__ X,
                                                  const __nv_bfloat16* __restrict__ whi,
                                                  const __nv_bfloat16* __restrict__ wlo,
                                                  __half* __restrict__ Out) {
    constexpr int NT2    = DOUT / 16;     // 8 or 4
    constexpr int STRIDE = 136;           // bf16 elems per smem row (pad 8)

    extern __shared__ __nv_bfloat16 bs[];
    __nv_bfloat16* Bh = bs;
    __nv_bfloat16* Bl = bs + DOUT * STRIDE;

    const int tid  = threadIdx.x;
    const int lane = tid & 31;
    const int wid  = tid >> 5;

    for (int t = tid; t < DOUT * 16; t += 256) {
        int n = t >> 4, c = t & 15;
        ((uint4*)(Bh + n * STRIDE))[c] = ((const uint4*)(whi + n * 128))[c];
        ((uint4*)(Bl + n * STRIDE))[c] = ((const uint4*)(wlo + n * 128))[c];
    }
    __syncthreads();

    const uint32_t bh_base = smem_u32(Bh);
    const uint32_t bl_base = smem_u32(Bl);

    const int r0 = blockIdx.x * 128 + wid * 16 + (lane >> 2);
    const int r1 = r0 + 8;
    const bool v0 = r0 < N_NODES, v1 = r1 < N_NODES;
    const int kc = (lane & 3) * 2;
    const XT* p0 = X + (size_t)r0 * 128 + kc;
    const XT* p1 = X + (size_t)r1 * 128 + kc;

    const uint32_t lm_row  = (lane & 7) + ((lane >> 4) << 3);
    const uint32_t lm_koff = ((lane >> 3) & 1) * 8;

    float acc[2 * NT2][4];
    #pragma unroll
    for (int i = 0; i < 2 * NT2; i++)
        #pragma unroll
        for (int j = 0; j < 4; j++) acc[i][j] = 0.0f;

    #pragma unroll
    for (int ks = 0; ks < 8; ks++) {
        const int k0 = ks * 16;
        float2 z = make_float2(0.f, 0.f);
        float2 x00 = v0 ? ldx2(p0 + k0)     : z;
        float2 x01 = v0 ? ldx2(p0 + k0 + 8) : z;
        float2 x10 = v1 ? ldx2(p1 + k0)     : z;
        float2 x11 = v1 ? ldx2(p1 + k0 + 8) : z;
        uint32_t ah[4], al[4];
        bf16_split(x00, ah[0], al[0]);
        bf16_split(x10, ah[1], al[1]);
        bf16_split(x01, ah[2], al[2]);
        bf16_split(x11, ah[3], al[3]);

        #pragma unroll
        for (int nt = 0; nt < NT2; nt++) {
            uint32_t off = ((nt * 16 + lm_row) * STRIDE + (uint32_t)k0 + lm_koff) * 2;
            uint32_t h0, h1, h2, h3, l0, l1, l2, l3;
            LDSM4(h0, h1, h2, h3, bh_base + off);
            LDSM4(l0, l1, l2, l3, bl_base + off);
            MMA16816(acc[2 * nt],     ah, h0, h1);
            MMA16816(acc[2 * nt],     ah, l0, l1);
            MMA16816(acc[2 * nt],     al, h0, h1);
            MMA16816(acc[2 * nt + 1], ah, h2, h3);
            MMA16816(acc[2 * nt + 1], ah, l2, l3);
            MMA16816(acc[2 * nt + 1], al, h2, h3);
        }
    }

    #pragma unroll
    for (int nt = 0; nt < NT2; nt++) {
        int n0 = nt * 16 + kc;
        if (v0) {
            *(__half2*)(Out + (size_t)r0 * DOUT + n0)     = __floats2half2_rn(acc[2 * nt][0],     acc[2 * nt][1]);
            *(__half2*)(Out + (size_t)r0 * DOUT + n0 + 8) = __floats2half2_rn(acc[2 * nt + 1][0], acc[2 * nt + 1][1]);
        }
        if (v1) {
            *(__half2*)(Out + (size_t)r1 * DOUT + n0)     = __floats2half2_rn(acc[2 * nt][2],     acc[2 * nt][3]);
            *(__half2*)(Out + (size_t)r1 * DOUT + n0 + 8) = __floats2half2_rn(acc[2 * nt + 1][2], acc[2 * nt + 1][3]);
        }
    }
}

// ---------------- SpMM 128-wide: ONE warp/node, 2 edges per iteration ------------------
// Lanes 0-15 gather edge j (16B each = full 256B row), lanes 16-31 gather edge j+1.
// Out-of-range shfl lanes carry ed=0 -> weight bits 0 -> contribute +0 (tail-safe).
template <bool RELU>
__global__ void __launch_bounds__(256) k_spmm128(const __half* __restrict__ T,
                                                 const float* __restrict__ bias,
                                                 __half* __restrict__ H) {
    const int node = blockIdx.x * 8 + (threadIdx.x >> 5);
    const int lane = threadIdx.x & 31;
    if (node >= N_NODES) return;
    const int deg = g_deg[node];
    const uint32_t* row = g_csr + ((size_t)node << PAD_LG);
    const int sub = lane >> 4;           // 0 or 1: which edge of the pair
    const int c   = lane & 15;           // 16B column group (cols c*8 .. c*8+7)

    float acc[8];
    #pragma unroll
    for (int k = 0; k < 8; k++) acc[k] = 0.f;

    for (int eb = 0; eb < deg; eb += 32) {
        int e = eb + lane;
        uint32_t ed = 0;
        if (e < deg) ed = row[e];
        int m = min(32, deg - eb);
        #pragma unroll 4
        for (int j = 0; j < m; j += 2) {
            uint32_t pe = __shfl_sync(0xffffffffu, ed, j + sub);
            int   sj = (int)(pe & 0xFFFFu);
            float wj = __half2float(__ushort_as_half((unsigned short)(pe >> 16)));
            uint4 u = *(const uint4*)(T + (size_t)sj * 128 + c * 8);
            float2 f0 = __half22float2(*reinterpret_cast<__half2*>(&u.x));
            float2 f1 = __half22float2(*reinterpret_cast<__half2*>(&u.y));
            float2 f2 = __half22float2(*reinterpret_cast<__half2*>(&u.z));
            float2 f3 = __half22float2(*reinterpret_cast<__half2*>(&u.w));
            acc[0] += wj * f0.x; acc[1] += wj * f0.y;
            acc[2] += wj * f1.x; acc[3] += wj * f1.y;
            acc[4] += wj * f2.x; acc[5] += wj * f2.y;
            acc[6] += wj * f3.x; acc[7] += wj * f3.y;
        }
    }
    // combine the two edge-subsets (lane L and L^16 cover the same columns)
    #pragma unroll
    for (int k = 0; k < 8; k++)
        acc[k] += __shfl_xor_sync(0xffffffffu, acc[k], 16);

    if (sub == 0) {
        float4 b0 = *(const float4*)(bias + c * 8);
        float4 b1 = *(const float4*)(bias + c * 8 + 4);
        acc[0] += b0.x; acc[1] += b0.y; acc[2] += b0.z; acc[3] += b0.w;
        acc[4] += b1.x; acc[5] += b1.y; acc[6] += b1.z; acc[7] += b1.w;
        if (RELU) {
            #pragma unroll
            for (int k = 0; k < 8; k++) acc[k] = fmaxf(acc[k], 0.f);
        }
        uint4 o;
        *reinterpret_cast<__half2*>(&o.x) = __floats2half2_rn(acc[0], acc[1]);
        *reinterpret_cast<__half2*>(&o.y) = __floats2half2_rn(acc[2], acc[3]);
        *reinterpret_cast<__half2*>(&o.z) = __floats2half2_rn(acc[4], acc[5]);
        *reinterpret_cast<__half2*>(&o.w) = __floats2half2_rn(acc[6], acc[7]);
        *(uint4*)(H + (size_t)node * 128 + c * 8) = o;
    }
}

// ---------------- SpMM 64-wide (fp32 out): ONE warp/node, 4 edges per iteration --------
// Lanes grouped by 8: group g handles edge j+g; lane covers 16B (8 halves).
__global__ void __launch_bounds__(256) k_spmm64(const __half* __restrict__ T,
                                                const float* __restrict__ bias,
                                                float* __restrict__ H) {
    const int node = blockIdx.x * 8 + (threadIdx.x >> 5);
    const int lane = threadIdx.x & 31;
    if (node >= N_NODES) return;
    const int deg = g_deg[node];
    const uint32_t* row = g_csr + ((size_t)node << PAD_LG);
    const int sub = lane >> 3;           // 0..3: which edge of the quad
    const int c   = lane & 7;            // 16B column group (cols c*8 .. c*8+7)

    float acc[8];
    #pragma unroll
    for (int k = 0; k < 8; k++) acc[k] = 0.f;

    for (int eb = 0; eb < deg; eb += 32) {
        int e = eb + lane;
        uint32_t ed = 0;
        if (e < deg) ed = row[e];
        int m = min(32, deg - eb);
        #pragma unroll 4
        for (int j = 0; j < m; j += 4) {
            uint32_t pe = __shfl_sync(0xffffffffu, ed, j + sub);
            int   sj = (int)(pe & 0xFFFFu);
            float wj = __half2float(__ushort_as_half((unsigned short)(pe >> 16)));
            uint4 u = *(const uint4*)(T + (size_t)sj * 64 + c * 8);
            float2 f0 = __half22float2(*reinterpret_cast<__half2*>(&u.x));
            float2 f1 = __half22float2(*reinterpret_cast<__half2*>(&u.y));
            float2 f2 = __half22float2(*reinterpret_cast<__half2*>(&u.z));
            float2 f3 = __half22float2(*reinterpret_cast<__half2*>(&u.w));
            acc[0] += wj * f0.x; acc[1] += wj * f0.y;
            acc[2] += wj * f1.x; acc[3] += wj * f1.y;
            acc[4] += wj * f2.x; acc[5] += wj * f2.y;
            acc[6] += wj * f3.x; acc[7] += wj * f3.y;
        }
    }
    // combine 4 edge-subsets (xor 8, then xor 16)
    #pragma unroll
    for (int k = 0; k < 8; k++) {
        acc[k] += __shfl_xor_sync(0xffffffffu, acc[k], 8);
        acc[k] += __shfl_xor_sync(0xffffffffu, acc[k], 16);
    }

    if (sub == 0) {
        float4 b0 = *(const float4*)(bias + c * 8);
        float4 b1 = *(const float4*)(bias + c * 8 + 4);
        acc[0] += b0.x; acc[1] += b0.y; acc[2] += b0.z; acc[3] += b0.w;
        acc[4] += b1.x; acc[5] += b1.y; acc[6] += b1.z; acc[7] += b1.w;
        float* o = H + (size_t)node * 64 + c * 8;
        *(float4*)o       = make_float4(acc[0], acc[1], acc[2], acc[3]);
        *(float4*)(o + 4) = make_float4(acc[4], acc[5], acc[6], acc[7]);
    }
}

// ---------------- launch ----------------
extern "C" void kernel_launch(void* const* d_in, const int* in_sizes, int n_in,
                              void* d_out, int out_size) {
    const float* x  = (const float*)d_in[0];
    const int*   ei = (const int*)  d_in[1];   // [2, E]: row0 = dst, row1 = src
    const float* ew = (const float*)d_in[2];
    const float* W1 = (const float*)d_in[3];
    const float* b1 = (const float*)d_in[4];
    const float* W2 = (const float*)d_in[5];
    const float* b2 = (const float*)d_in[6];
    const float* W3 = (const float*)d_in[7];
    const float* b3 = (const float*)d_in[8];
    float* out = (float*)d_out;

    void *pA, *pB, *ph1, *pl1, *ph2, *pl2, *ph3, *pl3;
    cudaGetSymbolAddress(&pA, g_bufA);
    cudaGetSymbolAddress(&pB, g_bufB);
    cudaGetSymbolAddress(&ph1, g_whi1); cudaGetSymbolAddress(&pl1, g_wlo1);
    cudaGetSymbolAddress(&ph2, g_whi2); cudaGetSymbolAddress(&pl2, g_wlo2);
    cudaGetSymbolAddress(&ph3, g_whi3); cudaGetSymbolAddress(&pl3, g_wlo3);
    __half* bufA = (__half*)pA;
    __half* bufB = (__half*)pB;
    __nv_bfloat16 *whi1 = (__nv_bfloat16*)ph1, *wlo1 = (__nv_bfloat16*)pl1;
    __nv_bfloat16 *whi2 = (__nv_bfloat16*)ph2, *wlo2 = (__nv_bfloat16*)pl2;
    __nv_bfloat16 *whi3 = (__nv_bfloat16*)ph3, *wlo3 = (__nv_bfloat16*)pl3;

    const int smem128 = 2 * 128 * 136 * 2;   // 69,632 B
    const int smem64  = 2 * 64  * 136 * 2;   // 34,816 B
    cudaFuncSetAttribute(k_gemm_mma<128, float>,  cudaFuncAttributeMaxDynamicSharedMemorySize, smem128);
    cudaFuncSetAttribute(k_gemm_mma<128, __half>, cudaFuncAttributeMaxDynamicSharedMemorySize, smem128);
    cudaFuncSetAttribute(k_gemm_mma<64,  __half>, cudaFuncAttributeMaxDynamicSharedMemorySize, smem64);

    // side stream + events (leaked deliberately: destroying during an active
    // capture is illegal, and kernel_launch runs only a handful of times)
    cudaStream_t s2;
    cudaStreamCreateWithFlags(&s2, cudaStreamNonBlocking);
    cudaEvent_t evFork, evJoin, evW23;
    cudaEventCreateWithFlags(&evFork, cudaEventDisableTiming);
    cudaEventCreateWithFlags(&evJoin, cudaEventDisableTiming);
    cudaEventCreateWithFlags(&evW23, cudaEventDisableTiming);

    const int e4_blocks   = (N_EDGES / 4 + 255) / 256;
    const int tiles       = (N_NODES + 127) / 128;   // 391
    const int spmm_blocks = (N_NODES + 7) / 8;       // 6250

    // ---- fork: branch B on s2 = warm X + wprep1 + GEMM1 ----
    cudaEventRecord(evFork, 0);
    cudaStreamWaitEvent(s2, evFork, 0);
    k_warm<<<1024, 256, 0, s2>>>(x);
    k_wprep<<<(128 * 128 + 255) / 256, 256, 0, s2>>>(W1, 128, whi1, wlo1);
    k_gemm_mma<128, float><<<tiles, 256, smem128, s2>>>(x, whi1, wlo1, bufA);
    cudaEventRecord(evJoin, s2);
    // wprep2/3 run on s2 during spmm1 (whi2/3 not read until gemm2/gemm3)
    k_wprep<<<(128 * 128 + 255) / 256, 256, 0, s2>>>(W2, 128, whi2, wlo2);
    k_wprep<<<(128 * 64 + 255) / 256, 256, 0, s2>>>(W3, 64, whi3, wlo3);
    cudaEventRecord(evW23, s2);

    // ---- branch A on origin stream = single-pass padded-CSR build ----
    k_scatter<<<e4_blocks, 256>>>(ei, ew);
    k_degcopy<<<(N_NODES + 255) / 256, 256>>>();

    // ---- join, then the serial layer chain ----
    cudaStreamWaitEvent(0, evJoin, 0);
    k_spmm128<true><<<spmm_blocks, 256>>>(bufA, b1, bufB);
    cudaStreamWaitEvent(0, evW23, 0);
    k_gemm_mma<128, __half><<<tiles, 256, smem128>>>(bufB, whi2, wlo2, bufA);
    k_spmm128<true><<<spmm_blocks, 256>>>(bufA, b2, bufB);
    k_gemm_mma<64, __half><<<tiles, 256, smem64>>>(bufB, whi3, wlo3, bufA);
    k_spmm64<<<spmm_blocks, 256>>>(bufA, b3, out);
}